// round 16
// baseline (speedup 1.0000x reference)
#include <cuda_runtime.h>

#define TT 100
#define BB 32768

// ---- frozen arithmetic (R5/R8/R13, passing, rel_err 5.5296e-4) ----
// Per neuron: NEON 4-lane dot as 2x f32x2 chains over float4 groups,
// pairwise reduce (l0+l1)+(l2+l3), scalar fma tail, bias after,
// LIF: fmaf(0.9,m,cur) - reset (reset from PREVIOUS mem), spike = nm>1.

typedef unsigned long long u64;

__device__ __forceinline__ u64 fma2(u64 a, u64 b, u64 c) {
    u64 d;
    asm("fma.rn.f32x2 %0, %1, %2, %3;" : "=l"(d) : "l"(a), "l"(b), "l"(c));
    return d;
}

__device__ __forceinline__ float reduce2x2(u64 a01, u64 a23) {
    float l0, l1, l2, l3;
    asm("mov.b64 {%0,%1}, %2;" : "=f"(l0), "=f"(l1) : "l"(a01));
    asm("mov.b64 {%0,%1}, %2;" : "=f"(l2), "=f"(l3) : "l"(a23));
    return __fadd_rn(__fadd_rn(l0, l1), __fadd_rn(l2, l3));
}

__global__ __launch_bounds__(32) void snn_kernel(
    const float* __restrict__ x,
    const float* __restrict__ w_s1, const float* __restrict__ b_s1,
    const float* __restrict__ w_s2, const float* __restrict__ b_s2,
    const float* __restrict__ w_c1, const float* __restrict__ b_c1,
    const float* __restrict__ w_co, const float* __restrict__ b_co,
    const float* __restrict__ w_ro, const float* __restrict__ b_ro,
    float* __restrict__ out)
{
    __shared__ __align__(16) float s_ws1[28 * 32];
    __shared__ __align__(16) float s_ws2[14 * 28];
    __shared__ __align__(16) float s_wc1[8 * 16];
    __shared__ __align__(16) float s_wco[3 * 8];
    __shared__ __align__(16) float s_wro[16];
    __shared__ float s_bs1[28], s_bs2[14], s_bc1[8], s_bco[3], s_bro[1];

    const int tid = threadIdx.x;
    for (int i = tid; i < 28 * 32; i += 32) s_ws1[i] = w_s1[i];
    for (int i = tid; i < 14 * 28; i += 32) s_ws2[i] = w_s2[i];
    for (int i = tid; i < 8 * 16;  i += 32) s_wc1[i] = (i % 16 < 14) ? w_c1[(i / 16) * 14 + (i % 16)] : 0.0f;
    for (int i = tid; i < 3 * 8;   i += 32) s_wco[i] = w_co[i];
    if (tid < 16) s_wro[tid] = (tid < 14) ? w_ro[tid] : 0.0f;
    for (int i = tid; i < 28; i += 32) s_bs1[i] = b_s1[i];
    for (int i = tid; i < 14; i += 32) s_bs2[i] = b_s2[i];
    for (int i = tid; i < 8;  i += 32) s_bc1[i] = b_c1[i];
    for (int i = tid; i < 3;  i += 32) s_bco[i] = b_co[i];
    if (tid == 0) s_bro[0] = b_ro[0];
    __syncthreads();

    const int b = blockIdx.x * 32 + tid;

    // ALL membranes in registers (constant-indexed via full unroll)
    float m1[28], m2[14], mc1[8], mco[3], mro;
    #pragma unroll
    for (int j = 0; j < 28; j++) m1[j] = 0.0f;
    #pragma unroll
    for (int j = 0; j < 14; j++) m2[j] = 0.0f;
    #pragma unroll
    for (int j = 0; j < 8;  j++) mc1[j] = 0.0f;
    mco[0] = mco[1] = mco[2] = 0.0f;
    mro = 0.0f;

    float* o_mco   = out;                          // (T,B,3)
    float* o_spkc1 = out + (size_t)TT * BB * 3;    // (T,B,8)
    float* o_mro   = out + (size_t)TT * BB * 11;   // (T,B,1)
    float* o_spk1  = out + (size_t)TT * BB * 12;   // (T,B,28)
    float* o_spk2  = out + (size_t)TT * BB * 40;   // (T,B,14)

    // x for t=0 (packed 16B groups: .x=(f0,f1) .y=(f2,f3))
    ulonglong2 xv[8];
    {
        const ulonglong2* xt = (const ulonglong2*)(x + (size_t)b * 32);
        #pragma unroll
        for (int i = 0; i < 8; i++) xv[i] = xt[i];
    }

    #pragma unroll 1
    for (int t = 0; t < TT; t++) {
        const size_t base = (size_t)t * BB + b;

        // ---- layer s1: 32 -> 28 (FULLY unrolled; membranes in regs) ----
        unsigned bits1 = 0;
        #pragma unroll
        for (int j = 0; j < 28; j++) {
            const ulonglong2* wr = (const ulonglong2*)&s_ws1[j * 32];
            u64 a01 = 0ull, a23 = 0ull;
            #pragma unroll
            for (int i = 0; i < 8; i++) {
                ulonglong2 w = wr[i];
                a01 = fma2(w.x, xv[i].x, a01);
                a23 = fma2(w.y, xv[i].y, a23);
            }
            float cur = __fadd_rn(reduce2x2(a01, a23), s_bs1[j]);
            float m   = m1[j];
            float nm  = __fadd_rn(fmaf(0.9f, m, cur), -((m > 1.0f) ? 1.0f : 0.0f));
            m1[j] = nm;
            bits1 |= ((nm > 1.0f) ? 1u : 0u) << j;
        }

        float spk1r[28];
        #pragma unroll
        for (int i = 0; i < 28; i++) spk1r[i] = ((bits1 >> i) & 1u) ? 1.0f : 0.0f;

        // ---- reload x for t+1 (xv dead; overlaps s2..ro compute) ----
        {
            int tn = (t + 1 < TT) ? (t + 1) : (TT - 1);
            const ulonglong2* xt2 = (const ulonglong2*)(x + ((size_t)tn * BB + b) * 32);
            #pragma unroll
            for (int i = 0; i < 8; i++) xv[i] = xt2[i];
        }

        // ---- layer s2: 28 -> 14 ----
        unsigned bits2 = 0;
        const ulonglong2* v1 = (const ulonglong2*)spk1r;
        #pragma unroll
        for (int j = 0; j < 14; j++) {
            const ulonglong2* wr = (const ulonglong2*)&s_ws2[j * 28];
            u64 a01 = 0ull, a23 = 0ull;
            #pragma unroll
            for (int i = 0; i < 7; i++) {
                ulonglong2 w = wr[i];
                a01 = fma2(w.x, v1[i].x, a01);
                a23 = fma2(w.y, v1[i].y, a23);
            }
            float cur = __fadd_rn(reduce2x2(a01, a23), s_bs2[j]);
            float m   = m2[j];
            float nm  = __fadd_rn(fmaf(0.9f, m, cur), -((m > 1.0f) ? 1.0f : 0.0f));
            m2[j] = nm;
            bits2 |= ((nm > 1.0f) ? 1u : 0u) << j;
        }

        float spk2r[14];
        #pragma unroll
        for (int i = 0; i < 14; i++) spk2r[i] = ((bits2 >> i) & 1u) ? 1.0f : 0.0f;

        // ---- layer c1: 14 -> 8 (3 vec groups + tail 12,13) ----
        unsigned bitsc = 0;
        const ulonglong2* v2 = (const ulonglong2*)spk2r;
        #pragma unroll
        for (int j = 0; j < 8; j++) {
            const ulonglong2* wr = (const ulonglong2*)&s_wc1[j * 16];
            u64 a01 = 0ull, a23 = 0ull;
            #pragma unroll
            for (int i = 0; i < 3; i++) {
                ulonglong2 w = wr[i];
                a01 = fma2(w.x, v2[i].x, a01);
                a23 = fma2(w.y, v2[i].y, a23);
            }
            float s = reduce2x2(a01, a23);
            s = fmaf(s_wc1[j * 16 + 12], spk2r[12], s);
            s = fmaf(s_wc1[j * 16 + 13], spk2r[13], s);
            float cur = __fadd_rn(s, s_bc1[j]);
            float m   = mc1[j];
            float nm  = __fadd_rn(fmaf(0.9f, m, cur), -((m > 1.0f) ? 1.0f : 0.0f));
            mc1[j] = nm;
            bitsc |= ((nm > 1.0f) ? 1u : 0u) << j;
        }

        float spkcr[8];
        #pragma unroll
        for (int i = 0; i < 8; i++) spkcr[i] = ((bitsc >> i) & 1u) ? 1.0f : 0.0f;

        // ---- layer co: 8 -> 3 ----
        {
            const ulonglong2* vc = (const ulonglong2*)spkcr;
            #pragma unroll
            for (int j = 0; j < 3; j++) {
                const ulonglong2* wr = (const ulonglong2*)&s_wco[j * 8];
                u64 a01 = 0ull, a23 = 0ull;
                #pragma unroll
                for (int i = 0; i < 2; i++) {
                    ulonglong2 w = wr[i];
                    a01 = fma2(w.x, vc[i].x, a01);
                    a23 = fma2(w.y, vc[i].y, a23);
                }
                float cur = __fadd_rn(reduce2x2(a01, a23), s_bco[j]);
                float m   = mco[j];
                float nm  = __fadd_rn(fmaf(0.9f, m, cur), -((m > 1.0f) ? 1.0f : 0.0f));
                mco[j] = nm;
            }
        }

        // ---- layer ro: 14 -> 1 ----
        {
            const ulonglong2* wr = (const ulonglong2*)s_wro;
            u64 a01 = 0ull, a23 = 0ull;
            #pragma unroll
            for (int i = 0; i < 3; i++) {
                ulonglong2 w = wr[i];
                a01 = fma2(w.x, v2[i].x, a01);
                a23 = fma2(w.y, v2[i].y, a23);
            }
            float s = reduce2x2(a01, a23);
            s = fmaf(s_wro[12], spk2r[12], s);
            s = fmaf(s_wro[13], spk2r[13], s);
            float cur = __fadd_rn(s, s_bro[0]);
            mro = __fadd_rn(fmaf(0.9f, mro, cur), -((mro > 1.0f) ? 1.0f : 0.0f));
        }

        // ---- stores (vectorized, coalesced) ----
        {
            float* p = o_mco + base * 3;
            p[0] = mco[0]; p[1] = mco[1]; p[2] = mco[2];
        }
        {
            float4* q = (float4*)(o_spkc1 + base * 8);
            q[0] = make_float4(spkcr[0], spkcr[1], spkcr[2], spkcr[3]);
            q[1] = make_float4(spkcr[4], spkcr[5], spkcr[6], spkcr[7]);
        }
        o_mro[base] = mro;
        {
            float4* r = (float4*)(o_spk1 + base * 28);
            #pragma unroll
            for (int j = 0; j < 7; j++)
                r[j] = make_float4(spk1r[4 * j], spk1r[4 * j + 1],
                                   spk1r[4 * j + 2], spk1r[4 * j + 3]);
        }
        {
            float2* s2 = (float2*)(o_spk2 + base * 14);
            #pragma unroll
            for (int j = 0; j < 7; j++)
                s2[j] = make_float2(spk2r[2 * j], spk2r[2 * j + 1]);
        }
    }
}

extern "C" void kernel_launch(void* const* d_in, const int* in_sizes, int n_in,
                              void* d_out, int out_size) {
    snn_kernel<<<BB / 32, 32>>>(
        (const float*)d_in[0],
        (const float*)d_in[1],  (const float*)d_in[2],
        (const float*)d_in[3],  (const float*)d_in[4],
        (const float*)d_in[5],  (const float*)d_in[6],
        (const float*)d_in[7],  (const float*)d_in[8],
        (const float*)d_in[9],  (const float*)d_in[10],
        (float*)d_out);
}

// round 17
// speedup vs baseline: 9.0523x; 9.0523x over previous
#include <cuda_runtime.h>

#define TT 100
#define BB 32768

// ---- frozen arithmetic (R5/R8/R13, passing, rel_err 5.5296e-4) ----
// Per neuron: NEON 4-lane dot as 2x f32x2 chains over float4 groups,
// pairwise reduce (l0+l1)+(l2+l3), scalar fma tail, bias after,
// LIF: fmaf(0.9,m,cur) - reset (reset from PREVIOUS mem), spike = nm>1.
// R17: weights/biases in __constant__ -> LDCU uniform port, off the L1/LSU pipe.

typedef unsigned long long u64;

__constant__ __align__(16) float c_ws1[28 * 32];
__constant__ __align__(16) float c_ws2[14 * 28];
__constant__ __align__(16) float c_wc1[8 * 14];
__constant__ __align__(16) float c_wco[3 * 8];
__constant__ __align__(16) float c_wro[14];
__constant__ float c_bs1[28], c_bs2[14], c_bc1[8], c_bco[3], c_bro[1];

__device__ __forceinline__ u64 fma2(u64 a, u64 b, u64 c) {
    u64 d;
    asm("fma.rn.f32x2 %0, %1, %2, %3;" : "=l"(d) : "l"(a), "l"(b), "l"(c));
    return d;
}

__device__ __forceinline__ float reduce2x2(u64 a01, u64 a23) {
    float l0, l1, l2, l3;
    asm("mov.b64 {%0,%1}, %2;" : "=f"(l0), "=f"(l1) : "l"(a01));
    asm("mov.b64 {%0,%1}, %2;" : "=f"(l2), "=f"(l3) : "l"(a23));
    return __fadd_rn(__fadd_rn(l0, l1), __fadd_rn(l2, l3));
}

// load a (w[2k], w[2k+1]) pair from constant as packed f32x2 operand
__device__ __forceinline__ u64 cpair(const float* p) {
    return *(const u64*)p;   // compile-time 8B-aligned constant address
}

__global__ __launch_bounds__(32) void snn_kernel(
    const float* __restrict__ x,
    float* __restrict__ out)
{
    // membranes paired: [neuron_pair][tid] = (m_{2k}, m_{2k+1})
    __shared__ __align__(8) float2 s_m1p[14][32];
    __shared__ __align__(8) float2 s_m2p[7][32];
    __shared__ __align__(8) float2 s_mc1p[4][32];

    const int tid = threadIdx.x;

    for (int k = 0; k < 14; k++) s_m1p[k][tid] = make_float2(0.0f, 0.0f);
    for (int k = 0; k < 7;  k++) s_m2p[k][tid] = make_float2(0.0f, 0.0f);
    for (int k = 0; k < 4;  k++) s_mc1p[k][tid] = make_float2(0.0f, 0.0f);
    float mco0 = 0.0f, mco1 = 0.0f, mco2 = 0.0f, mro = 0.0f;
    __syncthreads();

    const int b = blockIdx.x * 32 + tid;

    float* o_mco   = out;                          // (T,B,3)
    float* o_spkc1 = out + (size_t)TT * BB * 3;    // (T,B,8)
    float* o_mro   = out + (size_t)TT * BB * 11;   // (T,B,1)
    float* o_spk1  = out + (size_t)TT * BB * 12;   // (T,B,28)
    float* o_spk2  = out + (size_t)TT * BB * 40;   // (T,B,14)

    // prefetch x for t=0 as packed 16B groups: .x=(f0,f1) .y=(f2,f3)
    ulonglong2 xv[8];
    {
        const ulonglong2* xt = (const ulonglong2*)(x + (size_t)b * 32);
        #pragma unroll
        for (int i = 0; i < 8; i++) xv[i] = xt[i];
    }

    #pragma unroll 1
    for (int t = 0; t < TT; t++) {
        const size_t base = (size_t)t * BB + b;

        // ---- prefetch x for t+1 (clamped; overlaps this step's compute) ----
        ulonglong2 xn[8];
        {
            int tn = (t + 1 < TT) ? (t + 1) : (TT - 1);
            const ulonglong2* xt2 = (const ulonglong2*)(x + ((size_t)tn * BB + b) * 32);
            #pragma unroll
            for (int i = 0; i < 8; i++) xn[i] = xt2[i];
        }

        // ---- layer s1: 32 -> 28, neuron pairs ----
        unsigned bits1 = 0;
        #pragma unroll 7
        for (int k = 0; k < 14; k++) {
            const int j0 = 2 * k, j1 = 2 * k + 1;
            u64 a01 = 0ull, a23 = 0ull, b01 = 0ull, b23 = 0ull;
            #pragma unroll
            for (int i = 0; i < 8; i++) {
                a01 = fma2(cpair(c_ws1 + j0 * 32 + 4 * i),     xv[i].x, a01);
                a23 = fma2(cpair(c_ws1 + j0 * 32 + 4 * i + 2), xv[i].y, a23);
                b01 = fma2(cpair(c_ws1 + j1 * 32 + 4 * i),     xv[i].x, b01);
                b23 = fma2(cpair(c_ws1 + j1 * 32 + 4 * i + 2), xv[i].y, b23);
            }
            float cur0 = __fadd_rn(reduce2x2(a01, a23), c_bs1[j0]);
            float cur1 = __fadd_rn(reduce2x2(b01, b23), c_bs1[j1]);
            float2 mp  = s_m1p[k][tid];
            float rst0 = (mp.x > 1.0f) ? 1.0f : 0.0f;   // reset uses PREVIOUS mem
            float rst1 = (mp.y > 1.0f) ? 1.0f : 0.0f;
            float nm0  = __fadd_rn(fmaf(0.9f, mp.x, cur0), -rst0);
            float nm1  = __fadd_rn(fmaf(0.9f, mp.y, cur1), -rst1);
            s_m1p[k][tid] = make_float2(nm0, nm1);
            bits1 |= ((nm0 > 1.0f) ? 1u : 0u) << j0;
            bits1 |= ((nm1 > 1.0f) ? 1u : 0u) << j1;
        }

        float spk1r[28];
        #pragma unroll
        for (int i = 0; i < 28; i++) spk1r[i] = ((bits1 >> i) & 1u) ? 1.0f : 0.0f;

        // ---- layer s2: 28 -> 14, neuron pairs ----
        unsigned bits2 = 0;
        const ulonglong2* v1 = (const ulonglong2*)spk1r;
        #pragma unroll 7
        for (int k = 0; k < 7; k++) {
            const int j0 = 2 * k, j1 = 2 * k + 1;
            u64 a01 = 0ull, a23 = 0ull, b01 = 0ull, b23 = 0ull;
            #pragma unroll
            for (int i = 0; i < 7; i++) {
                a01 = fma2(cpair(c_ws2 + j0 * 28 + 4 * i),     v1[i].x, a01);
                a23 = fma2(cpair(c_ws2 + j0 * 28 + 4 * i + 2), v1[i].y, a23);
                b01 = fma2(cpair(c_ws2 + j1 * 28 + 4 * i),     v1[i].x, b01);
                b23 = fma2(cpair(c_ws2 + j1 * 28 + 4 * i + 2), v1[i].y, b23);
            }
            float cur0 = __fadd_rn(reduce2x2(a01, a23), c_bs2[j0]);
            float cur1 = __fadd_rn(reduce2x2(b01, b23), c_bs2[j1]);
            float2 mp  = s_m2p[k][tid];
            float rst0 = (mp.x > 1.0f) ? 1.0f : 0.0f;
            float rst1 = (mp.y > 1.0f) ? 1.0f : 0.0f;
            float nm0  = __fadd_rn(fmaf(0.9f, mp.x, cur0), -rst0);
            float nm1  = __fadd_rn(fmaf(0.9f, mp.y, cur1), -rst1);
            s_m2p[k][tid] = make_float2(nm0, nm1);
            bits2 |= ((nm0 > 1.0f) ? 1u : 0u) << j0;
            bits2 |= ((nm1 > 1.0f) ? 1u : 0u) << j1;
        }

        float spk2r[14];
        #pragma unroll
        for (int i = 0; i < 14; i++) spk2r[i] = ((bits2 >> i) & 1u) ? 1.0f : 0.0f;

        // ---- layer c1: 14 -> 8, neuron pairs (3 vec groups + tail 12,13) ----
        unsigned bitsc = 0;
        const ulonglong2* v2 = (const ulonglong2*)spk2r;
        #pragma unroll
        for (int k = 0; k < 4; k++) {
            const int j0 = 2 * k, j1 = 2 * k + 1;
            u64 a01 = 0ull, a23 = 0ull, b01 = 0ull, b23 = 0ull;
            #pragma unroll
            for (int i = 0; i < 3; i++) {
                a01 = fma2(cpair(c_wc1 + j0 * 14 + 4 * i),     v2[i].x, a01);
                a23 = fma2(cpair(c_wc1 + j0 * 14 + 4 * i + 2), v2[i].y, a23);
                b01 = fma2(cpair(c_wc1 + j1 * 14 + 4 * i),     v2[i].x, b01);
                b23 = fma2(cpair(c_wc1 + j1 * 14 + 4 * i + 2), v2[i].y, b23);
            }
            float s0 = reduce2x2(a01, a23);
            float s1 = reduce2x2(b01, b23);
            s0 = fmaf(c_wc1[j0 * 14 + 12], spk2r[12], s0);
            s0 = fmaf(c_wc1[j0 * 14 + 13], spk2r[13], s0);
            s1 = fmaf(c_wc1[j1 * 14 + 12], spk2r[12], s1);
            s1 = fmaf(c_wc1[j1 * 14 + 13], spk2r[13], s1);
            float cur0 = __fadd_rn(s0, c_bc1[j0]);
            float cur1 = __fadd_rn(s1, c_bc1[j1]);
            float2 mp  = s_mc1p[k][tid];
            float rst0 = (mp.x > 1.0f) ? 1.0f : 0.0f;
            float rst1 = (mp.y > 1.0f) ? 1.0f : 0.0f;
            float nm0  = __fadd_rn(fmaf(0.9f, mp.x, cur0), -rst0);
            float nm1  = __fadd_rn(fmaf(0.9f, mp.y, cur1), -rst1);
            s_mc1p[k][tid] = make_float2(nm0, nm1);
            bitsc |= ((nm0 > 1.0f) ? 1u : 0u) << j0;
            bitsc |= ((nm1 > 1.0f) ? 1u : 0u) << j1;
        }

        float spkcr[8];
        #pragma unroll
        for (int i = 0; i < 8; i++) spkcr[i] = ((bitsc >> i) & 1u) ? 1.0f : 0.0f;

        // ---- layer co: 8 -> 3 (mem in regs) ----
        {
            const ulonglong2* vc = (const ulonglong2*)spkcr;
            #pragma unroll
            for (int j = 0; j < 3; j++) {
                u64 a01 = 0ull, a23 = 0ull;
                #pragma unroll
                for (int i = 0; i < 2; i++) {
                    a01 = fma2(cpair(c_wco + j * 8 + 4 * i),     vc[i].x, a01);
                    a23 = fma2(cpair(c_wco + j * 8 + 4 * i + 2), vc[i].y, a23);
                }
                float cur = __fadd_rn(reduce2x2(a01, a23), c_bco[j]);
                float m   = (j == 0) ? mco0 : (j == 1) ? mco1 : mco2;
                float rst = (m > 1.0f) ? 1.0f : 0.0f;
                float nm  = __fadd_rn(fmaf(0.9f, m, cur), -rst);
                if (j == 0) mco0 = nm; else if (j == 1) mco1 = nm; else mco2 = nm;
            }
        }

        // ---- layer ro: 14 -> 1 (mem in reg) ----
        {
            u64 a01 = 0ull, a23 = 0ull;
            #pragma unroll
            for (int i = 0; i < 3; i++) {
                a01 = fma2(cpair(c_wro + 4 * i),     v2[i].x, a01);
                a23 = fma2(cpair(c_wro + 4 * i + 2), v2[i].y, a23);
            }
            float s = reduce2x2(a01, a23);
            s = fmaf(c_wro[12], spk2r[12], s);
            s = fmaf(c_wro[13], spk2r[13], s);
            float cur = __fadd_rn(s, c_bro[0]);
            float rst = (mro > 1.0f) ? 1.0f : 0.0f;
            mro = __fadd_rn(fmaf(0.9f, mro, cur), -rst);
        }

        // ---- stores (vectorized, coalesced) ----
        {
            float* p = o_mco + base * 3;
            p[0] = mco0; p[1] = mco1; p[2] = mco2;
        }
        {
            float4* q = (float4*)(o_spkc1 + base * 8);
            q[0] = make_float4(spkcr[0], spkcr[1], spkcr[2], spkcr[3]);
            q[1] = make_float4(spkcr[4], spkcr[5], spkcr[6], spkcr[7]);
        }
        o_mro[base] = mro;
        {
            float4* r = (float4*)(o_spk1 + base * 28);
            #pragma unroll
            for (int j = 0; j < 7; j++)
                r[j] = make_float4(spk1r[4 * j], spk1r[4 * j + 1],
                                   spk1r[4 * j + 2], spk1r[4 * j + 3]);
        }
        {
            float2* s2 = (float2*)(o_spk2 + base * 14);
            #pragma unroll
            for (int j = 0; j < 7; j++)
                s2[j] = make_float2(spk2r[2 * j], spk2r[2 * j + 1]);
        }

        // rotate prefetched x
        #pragma unroll
        for (int i = 0; i < 8; i++) xv[i] = xn[i];
    }
}

extern "C" void kernel_launch(void* const* d_in, const int* in_sizes, int n_in,
                              void* d_out, int out_size) {
    // D2D memcpy nodes (graph-capturable, allocation-free): weights -> constant bank
    cudaMemcpyToSymbolAsync(c_ws1, d_in[1],  28 * 32 * sizeof(float), 0, cudaMemcpyDeviceToDevice, 0);
    cudaMemcpyToSymbolAsync(c_bs1, d_in[2],  28 * sizeof(float),      0, cudaMemcpyDeviceToDevice, 0);
    cudaMemcpyToSymbolAsync(c_ws2, d_in[3],  14 * 28 * sizeof(float), 0, cudaMemcpyDeviceToDevice, 0);
    cudaMemcpyToSymbolAsync(c_bs2, d_in[4],  14 * sizeof(float),      0, cudaMemcpyDeviceToDevice, 0);
    cudaMemcpyToSymbolAsync(c_wc1, d_in[5],  8 * 14 * sizeof(float),  0, cudaMemcpyDeviceToDevice, 0);
    cudaMemcpyToSymbolAsync(c_bc1, d_in[6],  8 * sizeof(float),       0, cudaMemcpyDeviceToDevice, 0);
    cudaMemcpyToSymbolAsync(c_wco, d_in[7],  3 * 8 * sizeof(float),   0, cudaMemcpyDeviceToDevice, 0);
    cudaMemcpyToSymbolAsync(c_bco, d_in[8],  3 * sizeof(float),       0, cudaMemcpyDeviceToDevice, 0);
    cudaMemcpyToSymbolAsync(c_wro, d_in[9],  14 * sizeof(float),      0, cudaMemcpyDeviceToDevice, 0);
    cudaMemcpyToSymbolAsync(c_bro, d_in[10], 1 * sizeof(float),       0, cudaMemcpyDeviceToDevice, 0);

    snn_kernel<<<BB / 32, 32>>>((const float*)d_in[0], (float*)d_out);
}